// round 17
// baseline (speedup 1.0000x reference)
#include <cuda_runtime.h>

// OU Euler-Maruyama: x_{t+1} = a*x_t + b_t,  a = 1 - gamma*dt (const per chain).
// R16 = R15 resubmitted verbatim (R15 failed with a container-level
// "device busy" before launch — no data; this is the rerun, not a new
// variable). STREAM-COUNT test: 1024 warps, each warp runs TWO chains
// (2w, 2w+1) sequentially: per-warp stream 160KB (2x longer), half the
// concurrent streams, identical traffic/burst-size/registers.
// Compute per chain unchanged from R10/R13 best: group-of-4 interleaved
// constant-coefficient warp scans, unit-stride float4 tiles, PF=8 ring with
// front-batched 4KB refill bursts, __ldcs reads, evict-normal writes.

#define T_STEPS 20000
#define NV4     5000            // T_STEPS/4 float4s per chain
#define N_CHAIN 2048            // 32 * 64
#define PF      8               // prefetch depth (tiles)
#define NMAIN   19              // 19*8 = 152 tiles in main loop

__device__ __forceinline__ float4 load_tile(const float4* __restrict__ np,
                                            int tile, int lane) {
    int idx = tile * 32 + lane;
    if (idx < NV4) return __ldcs(np + idx);
    return make_float4(0.f, 0.f, 0.f, 0.f);
}

__global__ __launch_bounds__(64)
void oup_kernel(const float* __restrict__ theta,
                const float* __restrict__ noise,
                float*       __restrict__ out)
{
    const int warp = (blockIdx.x * blockDim.x + threadIdx.x) >> 5;
    const int lane = threadIdx.x & 31;
    if (warp >= N_CHAIN / 2) return;

    for (int cc = 0; cc < 2; ++cc) {
        const int chain = warp * 2 + cc;
        const int n = chain >> 6;                // chain-param row

        const float gamma = theta[n * 4 + 0];
        const float mu    = theta[n * 4 + 1];
        const float sigma = theta[n * 4 + 2];
        float x           = theta[n * 4 + 3];    // running state (carry)

        const float a   = 1.0f - gamma * 0.01f;  // dt = 0.01
        const float c0  = gamma * mu * 0.01f;
        const float ssd = sigma * 0.1f;          // sqrt(dt) = 0.1

        const float a2   = a * a;
        const float a4   = a2 * a2;
        const float a8   = a4 * a4;
        const float a16  = a8 * a8;
        const float a32  = a16 * a16;
        const float a64  = a32 * a32;
        const float a128 = a64 * a64;

        // a^(4*lane): exclusive-prefix coefficient for this lane's start state
        float alane = 1.0f;
        if (lane & 1)  alane *= a4;
        if (lane & 2)  alane *= a8;
        if (lane & 4)  alane *= a16;
        if (lane & 8)  alane *= a32;
        if (lane & 16) alane *= a64;

        const float4* __restrict__ np = (const float4*)(noise + (size_t)chain * T_STEPS);
        float4*       __restrict__ op = (float4*)(out + (size_t)chain * T_STEPS);

        // Prefetch ring (tiles 0..7 in-bounds)
        float4 buf[PF];
#pragma unroll
        for (int k = 0; k < PF; ++k) buf[k] = __ldcs(np + k * 32 + lane);

        // ---- 4-tile group: interleaved B-scans (ILP=4), serial carry ----
        auto group4 = [&](const float4* v, int tile0) {
            float b[4][4], B[4];
#pragma unroll
            for (int j = 0; j < 4; ++j) {
                b[j][0] = fmaf(ssd, v[j].x, c0);
                b[j][1] = fmaf(ssd, v[j].y, c0);
                b[j][2] = fmaf(ssd, v[j].z, c0);
                b[j][3] = fmaf(ssd, v[j].w, c0);
                float t = b[j][0];
                t = fmaf(a, t, b[j][1]);
                t = fmaf(a, t, b[j][2]);
                B[j] = fmaf(a, t, b[j][3]);
            }
#pragma unroll
            for (int s = 0; s < 5; ++s) {
                const int   d = 1 << s;
                const float w = (s == 0) ? a4 : (s == 1) ? a8 : (s == 2) ? a16
                              : (s == 3) ? a32 : a64;
                float t0 = __shfl_up_sync(0xFFFFFFFFu, B[0], d);
                float t1 = __shfl_up_sync(0xFFFFFFFFu, B[1], d);
                float t2 = __shfl_up_sync(0xFFFFFFFFu, B[2], d);
                float t3 = __shfl_up_sync(0xFFFFFFFFu, B[3], d);
                if (lane >= d) {
                    B[0] = fmaf(w, t0, B[0]);
                    B[1] = fmaf(w, t1, B[1]);
                    B[2] = fmaf(w, t2, B[2]);
                    B[3] = fmaf(w, t3, B[3]);
                }
            }
            float Bexcl[4], Btop[4];
#pragma unroll
            for (int j = 0; j < 4; ++j) {
                Bexcl[j] = __shfl_up_sync(0xFFFFFFFFu, B[j], 1);
                if (lane == 0) Bexcl[j] = 0.0f;
                Btop[j] = __shfl_sync(0xFFFFFFFFu, B[j], 31);
            }
#pragma unroll
            for (int j = 0; j < 4; ++j) {
                const float xs = fmaf(alane, x, Bexcl[j]);
                const float y0 = fmaf(a, xs, b[j][0]);
                const float y1 = fmaf(a, y0, b[j][1]);
                const float y2 = fmaf(a, y1, b[j][2]);
                const float y3 = fmaf(a, y2, b[j][3]);
                op[(tile0 + j) * 32 + lane] = make_float4(y0, y1, y2, y3);
                x = fmaf(a128, x, Btop[j]);
            }
        };

        // Main: 19 macro-iters; all 8 refills front-batched (4KB burst)
        for (int mi = 0; mi < NMAIN; ++mi) {
            const int i0 = mi * PF;
            float4 v[PF];
#pragma unroll
            for (int k = 0; k < PF; ++k) v[k] = buf[k];
#pragma unroll
            for (int k = 0; k < PF; ++k)
                buf[k] = load_tile(np, i0 + PF + k, lane);
            group4(v,     i0);
            group4(v + 4, i0 + 4);
        }
        // Tiles 152..155 from ring (in-bounds: 156*32 = 4992 <= 5000)
        {
            float4 v[4];
#pragma unroll
            for (int j = 0; j < 4; ++j) v[j] = buf[j];
            group4(v, NMAIN * PF);
        }
        // Tail tile 156 (partial: lanes with idx < 5000)
        {
            const float4 v = buf[4];
            const float b0 = fmaf(ssd, v.x, c0);
            const float b1 = fmaf(ssd, v.y, c0);
            const float b2 = fmaf(ssd, v.z, c0);
            const float b3 = fmaf(ssd, v.w, c0);
            float B = b0;
            B = fmaf(a, B, b1);
            B = fmaf(a, B, b2);
            B = fmaf(a, B, b3);
            float t;
            t = __shfl_up_sync(0xFFFFFFFFu, B, 1);  if (lane >= 1)  B = fmaf(a4,  t, B);
            t = __shfl_up_sync(0xFFFFFFFFu, B, 2);  if (lane >= 2)  B = fmaf(a8,  t, B);
            t = __shfl_up_sync(0xFFFFFFFFu, B, 4);  if (lane >= 4)  B = fmaf(a16, t, B);
            t = __shfl_up_sync(0xFFFFFFFFu, B, 8);  if (lane >= 8)  B = fmaf(a32, t, B);
            t = __shfl_up_sync(0xFFFFFFFFu, B, 16); if (lane >= 16) B = fmaf(a64, t, B);
            float Bexcl = __shfl_up_sync(0xFFFFFFFFu, B, 1);
            if (lane == 0) Bexcl = 0.0f;
            const float xs = fmaf(alane, x, Bexcl);
            const float y0 = fmaf(a, xs, b0);
            const float y1 = fmaf(a, y0, b1);
            const float y2 = fmaf(a, y1, b2);
            const float y3 = fmaf(a, y2, b3);
            const int idx = (NMAIN * PF + 4) * 32 + lane;
            if (idx < NV4) op[idx] = make_float4(y0, y1, y2, y3);
        }
    }
}

extern "C" void kernel_launch(void* const* d_in, const int* in_sizes, int n_in,
                              void* d_out, int out_size)
{
    const float* theta = (const float*)d_in[0];   // [32,4]
    const float* noise = (const float*)d_in[1];   // [32,64,20000]
    float* out = (float*)d_out;                   // [32,64,20000]
    (void)in_sizes; (void)n_in; (void)out_size;
    // 1024 warps (one per 2 chains) in 64-thread CTAs -> 512 blocks
    oup_kernel<<<N_CHAIN / 4, 64>>>(theta, noise, out);
}